// round 2
// baseline (speedup 1.0000x reference)
#include <cuda_runtime.h>
#include <cstdint>

#define L      2048
#define C_IN   16
#define GROUPS 4
#define NEG_INF -1000000000.0f

// Scratch for sparsemax probabilities (allowed: __device__ global array).
__device__ float g_probs[(size_t)C_IN * L * L];

// ---------------------------------------------------------------------------
// Kernel 1: row-wise sparsemax with causal mask.
// One block (256 threads) per (channel, row). Row cached in registers
// (8 values/thread). Michelot's exact algorithm seeded at tau = rowmax - 1.
// ---------------------------------------------------------------------------
__global__ __launch_bounds__(256) void sparsemax_kernel(const float* __restrict__ scores)
{
    const int row = blockIdx.x;
    const int ch  = blockIdx.y;
    const int tid = threadIdx.x;
    const size_t base = ((size_t)ch * L + row) * (size_t)L;

    float z[8];
#pragma unroll
    for (int k = 0; k < 8; k++) {
        const int j = tid + k * 256;
        z[k] = (j <= row) ? scores[base + j] : NEG_INF;
    }

    __shared__ float swarp[8];
    __shared__ float ssum[8];
    __shared__ float scnt[8];
    __shared__ float s_tau;
    __shared__ int   s_done;

    // ---- row max reduce ----
    float m = z[0];
#pragma unroll
    for (int k = 1; k < 8; k++) m = fmaxf(m, z[k]);
#pragma unroll
    for (int o = 16; o > 0; o >>= 1) m = fmaxf(m, __shfl_down_sync(0xffffffffu, m, o));
    if ((tid & 31) == 0) swarp[tid >> 5] = m;
    __syncthreads();
    if (tid == 0) {
        float mm = swarp[0];
#pragma unroll
        for (int w = 1; w < 8; w++) mm = fmaxf(mm, swarp[w]);
        s_tau = mm - 1.0f;   // tau* is guaranteed in [max-1, max)
    }
    __syncthreads();
    float tau = s_tau;

    // ---- Michelot iterations (exact, monotone, few needed) ----
    int prev0 = -1;  // meaningful only on thread 0
    for (int it = 0; it < 32; it++) {
        float sum = 0.0f, cnt = 0.0f;
#pragma unroll
        for (int k = 0; k < 8; k++) {
            if (z[k] > tau) { sum += z[k]; cnt += 1.0f; }
        }
#pragma unroll
        for (int o = 16; o > 0; o >>= 1) {
            sum += __shfl_down_sync(0xffffffffu, sum, o);
            cnt += __shfl_down_sync(0xffffffffu, cnt, o);
        }
        if ((tid & 31) == 0) { ssum[tid >> 5] = sum; scnt[tid >> 5] = cnt; }
        __syncthreads();
        if (tid == 0) {
            float S = 0.0f, C = 0.0f;
#pragma unroll
            for (int w = 0; w < 8; w++) { S += ssum[w]; C += scnt[w]; }
            const int ci = (int)C;           // C <= 2048, exact in fp32
            s_tau  = (S - 1.0f) / C;         // C >= 1 always (diagonal valid)
            s_done = (ci == prev0) ? 1 : 0;  // support stable -> converged
            prev0  = ci;
        }
        __syncthreads();
        tau = s_tau;
        if (s_done) break;
    }

    // ---- write probs (only the causal prefix; rest is never read) ----
#pragma unroll
    for (int k = 0; k < 8; k++) {
        const int j = tid + k * 256;
        if (j <= row) g_probs[base + j] = fmaxf(z[k] - tau, 0.0f);
    }
}

// ---------------------------------------------------------------------------
// Kernel 2: grouped 3x3 conv + bias + causal zero.
// One block (256 threads) per (output row i, group g).
// Stages 4 in-channels x 3 rows (with column halo) into smem,
// each thread produces 4 out-channels x 8 contiguous columns.
// ---------------------------------------------------------------------------
#define TSTRIDE 2052   // 2050 used (j=-1..2048) padded for 16B alignment

__global__ __launch_bounds__(256) void conv_kernel(const float* __restrict__ weight,
                                                   const float* __restrict__ bias,
                                                   float* __restrict__ out)
{
    extern __shared__ float smem[];
    float* tile = smem;                       // [4][3][TSTRIDE]
    float* wsm  = smem + 4 * 3 * TSTRIDE;     // [4 oc][4 ic][3][3] = 144
    float* bsm  = wsm + 144;                  // [4]

    const int i   = blockIdx.x;   // output row
    const int g   = blockIdx.y;   // group
    const int tid = threadIdx.x;

    if (tid < 144) {
        const int o = tid / 36;
        const int r = tid % 36;
        wsm[tid] = weight[(size_t)(g * 4 + o) * 36 + r];
    }
    if (tid < 4) bsm[tid] = bias[g * 4 + tid];

    // stage: rows i-1, i, i+1 of the 4 input channels; mask j>r (and OOB rows) to 0
#pragma unroll
    for (int ic = 0; ic < 4; ic++) {
        const int gc = g * 4 + ic;
#pragma unroll
        for (int dr = 0; dr < 3; dr++) {
            const int r = i + dr - 1;
            float* dst = tile + (ic * 3 + dr) * TSTRIDE;
            const bool rowok = (r >= 0) && (r < L);
            const size_t rb = ((size_t)gc * L + (rowok ? r : 0)) * (size_t)L;
            const int jmax = rowok ? r : -1;
            for (int mcol = tid; mcol < 2050; mcol += 256) {
                const int j = mcol - 1;
                float v = 0.0f;
                if (j >= 0 && j <= jmax) v = g_probs[rb + j];
                dst[mcol] = v;
            }
        }
    }
    __syncthreads();

    const int j0 = tid * 8;
    float acc[4][8];
#pragma unroll
    for (int o = 0; o < 4; o++)
#pragma unroll
        for (int x = 0; x < 8; x++) acc[o][x] = 0.0f;

#pragma unroll
    for (int ic = 0; ic < 4; ic++) {
#pragma unroll
        for (int dr = 0; dr < 3; dr++) {
            const float* src = tile + (ic * 3 + dr) * TSTRIDE + j0; // 32B aligned
            float s[10];
            {
                const float4 a = *reinterpret_cast<const float4*>(src);
                const float4 b = *reinterpret_cast<const float4*>(src + 4);
                s[0] = a.x; s[1] = a.y; s[2] = a.z; s[3] = a.w;
                s[4] = b.x; s[5] = b.y; s[6] = b.z; s[7] = b.w;
                s[8] = src[8]; s[9] = src[9];
            }
#pragma unroll
            for (int o = 0; o < 4; o++) {
                const int wb = ((o * 4 + ic) * 3 + dr) * 3;
                const float w0 = wsm[wb + 0];
                const float w1 = wsm[wb + 1];
                const float w2 = wsm[wb + 2];
#pragma unroll
                for (int x = 0; x < 8; x++)
                    acc[o][x] = fmaf(s[x], w0, fmaf(s[x + 1], w1, fmaf(s[x + 2], w2, acc[o][x])));
            }
        }
    }

    // bias + causal mask + vectorized store (covers every output element)
#pragma unroll
    for (int o = 0; o < 4; o++) {
        const size_t ob = ((size_t)(g * 4 + o) * L + i) * (size_t)L + j0;
        const float b = bsm[o];
        float v[8];
#pragma unroll
        for (int x = 0; x < 8; x++)
            v[x] = (j0 + x <= i) ? (acc[o][x] + b) : 0.0f;
        float4 v0, v1;
        v0.x = v[0]; v0.y = v[1]; v0.z = v[2]; v0.w = v[3];
        v1.x = v[4]; v1.y = v[5]; v1.z = v[6]; v1.w = v[7];
        *reinterpret_cast<float4*>(out + ob)     = v0;
        *reinterpret_cast<float4*>(out + ob + 4) = v1;
    }
}

// ---------------------------------------------------------------------------
extern "C" void kernel_launch(void* const* d_in, const int* in_sizes, int n_in,
                              void* d_out, int out_size)
{
    const float* scores = (const float*)d_in[0];
    const float* weight = (const float*)d_in[1];
    const float* bias   = (const float*)d_in[2];
    float* out = (float*)d_out;

    sparsemax_kernel<<<dim3(L, C_IN), 256>>>(scores);

    const size_t smem_bytes = (size_t)(4 * 3 * TSTRIDE + 144 + 4) * sizeof(float);
    cudaFuncSetAttribute(conv_kernel, cudaFuncAttributeMaxDynamicSharedMemorySize,
                         (int)smem_bytes);
    conv_kernel<<<dim3(L, GROUPS), 256, smem_bytes>>>(weight, bias, out);
}

// round 3
// speedup vs baseline: 1.3052x; 1.3052x over previous
#include <cuda_runtime.h>
#include <cstdint>

#define L      2048
#define C_IN   16
#define GROUPS 4
#define NEG_INF -1000000000.0f

// Sparsemax probabilities. Zero-initialized device global; sparsemax only ever
// writes j <= row, so the strict upper triangle is PERMANENTLY zero. The conv
// staging exploits this: no causal masking needed on reads.
__device__ float g_probs[(size_t)C_IN * L * L];

// ---------------------------------------------------------------------------
// Kernel 1: row-wise sparsemax with causal mask. One block per (channel,row).
// Vectorized float4 I/O: thread t owns cols [8t, 8t+8).
// Michelot's exact algorithm seeded at tau = rowmax - 1.
// ---------------------------------------------------------------------------
__global__ __launch_bounds__(256) void sparsemax_kernel(const float* __restrict__ scores)
{
    const int row = blockIdx.x;
    const int ch  = blockIdx.y;
    const int tid = threadIdx.x;
    const size_t base = ((size_t)ch * L + row) * (size_t)L;
    const int j0  = tid * 8;
    const int rem = row - j0;            // valid elements: x <= rem

    float z[8];
    if (rem >= 7) {                      // fully valid: two aligned float4 loads
        const float4 a = *reinterpret_cast<const float4*>(scores + base + j0);
        const float4 b = *reinterpret_cast<const float4*>(scores + base + j0 + 4);
        z[0]=a.x; z[1]=a.y; z[2]=a.z; z[3]=a.w;
        z[4]=b.x; z[5]=b.y; z[6]=b.z; z[7]=b.w;
    } else {
#pragma unroll
        for (int x = 0; x < 8; x++)
            z[x] = (x <= rem) ? scores[base + j0 + x] : NEG_INF;
    }

    __shared__ float swarp[8];
    __shared__ float ssum[8];
    __shared__ float scnt[8];
    __shared__ float s_tau;
    __shared__ int   s_done;

    // ---- row max reduce ----
    float m = z[0];
#pragma unroll
    for (int k = 1; k < 8; k++) m = fmaxf(m, z[k]);
#pragma unroll
    for (int o = 16; o > 0; o >>= 1) m = fmaxf(m, __shfl_xor_sync(0xffffffffu, m, o));
    if ((tid & 31) == 0) swarp[tid >> 5] = m;
    __syncthreads();
    if (tid == 0) {
        float mm = swarp[0];
#pragma unroll
        for (int w = 1; w < 8; w++) mm = fmaxf(mm, swarp[w]);
        s_tau = mm - 1.0f;   // tau* is guaranteed in [max-1, max)
    }
    __syncthreads();
    float tau = s_tau;

    // ---- Michelot iterations (exact, monotone, few needed) ----
    int prev0 = -1;  // meaningful only on thread 0
    for (int it = 0; it < 32; it++) {
        float sum = 0.0f, cnt = 0.0f;
#pragma unroll
        for (int k = 0; k < 8; k++) {
            if (z[k] > tau) { sum += z[k]; cnt += 1.0f; }
        }
#pragma unroll
        for (int o = 16; o > 0; o >>= 1) {
            sum += __shfl_xor_sync(0xffffffffu, sum, o);
            cnt += __shfl_xor_sync(0xffffffffu, cnt, o);
        }
        if ((tid & 31) == 0) { ssum[tid >> 5] = sum; scnt[tid >> 5] = cnt; }
        __syncthreads();
        if (tid == 0) {
            float S = 0.0f, C = 0.0f;
#pragma unroll
            for (int w = 0; w < 8; w++) { S += ssum[w]; C += scnt[w]; }
            const int ci = (int)C;           // C <= 2048, exact in fp32
            s_tau  = (S - 1.0f) / C;         // C >= 1 always (diagonal valid)
            s_done = (ci == prev0) ? 1 : 0;  // support stable -> converged
            prev0  = ci;
        }
        __syncthreads();
        tau = s_tau;
        if (s_done) break;
    }

    // ---- write probs; NEVER write j > row (upper-triangle-zero invariant) ----
    if (rem >= 7) {
        float4 a, b;
        a.x = fmaxf(z[0]-tau, 0.0f); a.y = fmaxf(z[1]-tau, 0.0f);
        a.z = fmaxf(z[2]-tau, 0.0f); a.w = fmaxf(z[3]-tau, 0.0f);
        b.x = fmaxf(z[4]-tau, 0.0f); b.y = fmaxf(z[5]-tau, 0.0f);
        b.z = fmaxf(z[6]-tau, 0.0f); b.w = fmaxf(z[7]-tau, 0.0f);
        *reinterpret_cast<float4*>(g_probs + base + j0)     = a;
        *reinterpret_cast<float4*>(g_probs + base + j0 + 4) = b;
    } else {
#pragma unroll
        for (int x = 0; x < 8; x++)
            if (x <= rem) g_probs[base + j0 + x] = fmaxf(z[x] - tau, 0.0f);
    }
}

// ---------------------------------------------------------------------------
// Kernel 2: grouped 3x3 conv + bias + causal zero, column-tiled.
// Block = (col-tile t of 1024, output row i, group g); 256 threads.
// Thread = 2 out-channels x 8 cols; all 72 weights in registers.
// smem: 12 planes (4 ic x 3 rows) x TS floats -> ~49.9 KB -> 4 blocks/SM.
// ---------------------------------------------------------------------------
#define TJ 1024
#define TS 1040          // plane stride: halo-L at idx 3, interior 4..1027, halo-R at 1028

__global__ __launch_bounds__(256) void conv_kernel(const float* __restrict__ weight,
                                                   const float* __restrict__ bias,
                                                   float* __restrict__ out)
{
    extern __shared__ float smem[];   // [12][TS]

    const int t   = blockIdx.x;       // col tile
    const int i   = blockIdx.y;       // output row
    const int g   = blockIdx.z;       // group
    const int tid = threadIdx.x;
    const int j0  = t * TJ;

    const int half = tid >> 7;            // 0: oc {0,1}, 1: oc {2,3}
    const int c    = (tid & 127) * 8;     // col offset within tile, 0..1016

    // ---- fast path: tile entirely above the diagonal -> zeros ----
    if (j0 > i) {
        const float4 zq = make_float4(0.f, 0.f, 0.f, 0.f);
#pragma unroll
        for (int o = 0; o < 2; o++) {
            const int ocg = g * 4 + half * 2 + o;
            float* ob = out + ((size_t)ocg * L + i) * (size_t)L + j0 + c;
            *reinterpret_cast<float4*>(ob)     = zq;
            *reinterpret_cast<float4*>(ob + 4) = zq;
        }
        return;
    }

    // ---- weights into registers (72 per thread: 2 oc x 4 ic x 3 x 3) ----
    float wreg[72];
#pragma unroll
    for (int o = 0; o < 2; o++)
#pragma unroll
        for (int r36 = 0; r36 < 36; r36++)
            wreg[o * 36 + r36] = __ldg(&weight[(size_t)(g * 4 + half * 2 + o) * 36 + r36]);

    // ---- stage 12 planes; no masking needed (upper triangle of g_probs == 0) ----
#pragma unroll
    for (int p = 0; p < 12; p++) {
        const int ic = p >> 2 & 3;            // p = ic*3 + dr
        // (compute ic, dr exactly:)
        const int icc = p / 3;
        const int dr  = p - icc * 3;
        const int r   = i + dr - 1;
        float4 v = make_float4(0.f, 0.f, 0.f, 0.f);
        if (r >= 0 && r < L) {
            const float4* src = reinterpret_cast<const float4*>(
                g_probs + ((size_t)(g * 4 + icc) * L + r) * (size_t)L + j0);
            v = src[tid];                      // cols j0+4*tid .. +3, aligned
        }
        *reinterpret_cast<float4*>(smem + p * TS + 4 + 4 * tid) = v;
        (void)ic;
    }
    // halos: 24 threads handle left (j0-1) and right (j0+TJ) columns
    if (tid < 24) {
        const int p    = tid >> 1;
        const int side = tid & 1;
        const int icc  = p / 3;
        const int dr   = p - icc * 3;
        const int r    = i + dr - 1;
        const int j    = side ? (j0 + TJ) : (j0 - 1);
        float v = 0.0f;
        if (r >= 0 && r < L && j >= 0 && j < L)
            v = g_probs[((size_t)(g * 4 + icc) * L + r) * (size_t)L + j];
        smem[p * TS + (side ? (TJ + 4) : 3)] = v;
    }
    __syncthreads();

    // ---- accumulate 2 oc x 8 cols ----
    float acc[2][8];
#pragma unroll
    for (int o = 0; o < 2; o++)
#pragma unroll
        for (int x = 0; x < 8; x++) acc[o][x] = 0.0f;

#pragma unroll
    for (int icc = 0; icc < 4; icc++) {
#pragma unroll
        for (int dr = 0; dr < 3; dr++) {
            const float* pl = smem + (icc * 3 + dr) * TS;
            float s[10];
            s[0] = pl[c + 3];                                   // col c-1
            const float4 A = *reinterpret_cast<const float4*>(pl + c + 4);  // c..c+3
            const float4 B = *reinterpret_cast<const float4*>(pl + c + 8);  // c+4..c+7
            s[1]=A.x; s[2]=A.y; s[3]=A.z; s[4]=A.w;
            s[5]=B.x; s[6]=B.y; s[7]=B.z; s[8]=B.w;
            s[9] = pl[c + 12];                                  // col c+8
#pragma unroll
            for (int o = 0; o < 2; o++) {
                const int wb = o * 36 + icc * 9 + dr * 3;
                const float w0 = wreg[wb + 0];
                const float w1 = wreg[wb + 1];
                const float w2 = wreg[wb + 2];
#pragma unroll
                for (int x = 0; x < 8; x++)
                    acc[o][x] = fmaf(s[x], w0, fmaf(s[x+1], w1, fmaf(s[x+2], w2, acc[o][x])));
            }
        }
    }

    // ---- bias + causal mask + store ----
    const int jc = j0 + c;
#pragma unroll
    for (int o = 0; o < 2; o++) {
        const int ocg = g * 4 + half * 2 + o;
        const float b = __ldg(&bias[ocg]);
        float v[8];
#pragma unroll
        for (int x = 0; x < 8; x++)
            v[x] = (jc + x <= i) ? (acc[o][x] + b) : 0.0f;
        float4 v0, v1;
        v0.x=v[0]; v0.y=v[1]; v0.z=v[2]; v0.w=v[3];
        v1.x=v[4]; v1.y=v[5]; v1.z=v[6]; v1.w=v[7];
        float* ob = out + ((size_t)ocg * L + i) * (size_t)L + jc;
        *reinterpret_cast<float4*>(ob)     = v0;
        *reinterpret_cast<float4*>(ob + 4) = v1;
    }
}

// ---------------------------------------------------------------------------
extern "C" void kernel_launch(void* const* d_in, const int* in_sizes, int n_in,
                              void* d_out, int out_size)
{
    const float* scores = (const float*)d_in[0];
    const float* weight = (const float*)d_in[1];
    const float* bias   = (const float*)d_in[2];
    float* out = (float*)d_out;

    sparsemax_kernel<<<dim3(L, C_IN), 256>>>(scores);

    const size_t smem_bytes = (size_t)(12 * TS) * sizeof(float);   // 49,920 B
    cudaFuncSetAttribute(conv_kernel, cudaFuncAttributeMaxDynamicSharedMemorySize,
                         (int)smem_bytes);
    conv_kernel<<<dim3(L / TJ, L, GROUPS), 256, smem_bytes>>>(weight, bias, out);
}

// round 4
// speedup vs baseline: 1.8397x; 1.4095x over previous
#include <cuda_runtime.h>
#include <cstdint>

#define L      2048
#define C_IN   16
#define GROUPS 4
#define NEG_INF -1000000000.0f

// Compressed sparsemax output: per (ch,row) a list of (col,val) nonzeros.
// Full-stride allocation => no overflow possible for any input.
// .x = column index as int bits, .y = prob value.
__device__ float2 g_list[(size_t)C_IN * L * L];
__device__ int    g_cnt[C_IN * L];

// ---------------------------------------------------------------------------
// Kernel 1: row-wise sparsemax (causal) -> compressed nonzero list.
// One block (256 thr) per (channel,row); thread t owns cols [8t, 8t+8).
// Michelot's exact algorithm seeded at tau = rowmax - 1.
// Compaction is atomics-free (ballot + prefix) => deterministic output order.
// ---------------------------------------------------------------------------
__global__ __launch_bounds__(256) void sparsemax_kernel(const float* __restrict__ scores)
{
    const int row = blockIdx.x;
    const int ch  = blockIdx.y;
    const int tid = threadIdx.x;
    const int lane = tid & 31;
    const int warp = tid >> 5;
    const size_t base = ((size_t)ch * L + row) * (size_t)L;
    const int j0  = tid * 8;
    const int rem = row - j0;            // valid elements: x <= rem

    float z[8];
    if (rem >= 7) {                      // fully valid: two aligned float4 loads
        const float4 a = *reinterpret_cast<const float4*>(scores + base + j0);
        const float4 b = *reinterpret_cast<const float4*>(scores + base + j0 + 4);
        z[0]=a.x; z[1]=a.y; z[2]=a.z; z[3]=a.w;
        z[4]=b.x; z[5]=b.y; z[6]=b.z; z[7]=b.w;
    } else {
#pragma unroll
        for (int x = 0; x < 8; x++)
            z[x] = (x <= rem) ? scores[base + j0 + x] : NEG_INF;
    }

    __shared__ float swarp[8];
    __shared__ float ssum[8];
    __shared__ float scnt[8];
    __shared__ int   siwarp[8];
    __shared__ float s_tau;
    __shared__ int   s_done;

    // ---- row max reduce ----
    float m = z[0];
#pragma unroll
    for (int k = 1; k < 8; k++) m = fmaxf(m, z[k]);
#pragma unroll
    for (int o = 16; o > 0; o >>= 1) m = fmaxf(m, __shfl_xor_sync(0xffffffffu, m, o));
    if (lane == 0) swarp[warp] = m;
    __syncthreads();
    if (tid == 0) {
        float mm = swarp[0];
#pragma unroll
        for (int w = 1; w < 8; w++) mm = fmaxf(mm, swarp[w]);
        s_tau = mm - 1.0f;   // tau* is guaranteed in [max-1, max)
    }
    __syncthreads();
    float tau = s_tau;

    // ---- Michelot iterations (exact, monotone, few needed) ----
    int prev0 = -1;  // meaningful only on thread 0
    for (int it = 0; it < 32; it++) {
        float sum = 0.0f, cnt = 0.0f;
#pragma unroll
        for (int k = 0; k < 8; k++) {
            if (z[k] > tau) { sum += z[k]; cnt += 1.0f; }
        }
#pragma unroll
        for (int o = 16; o > 0; o >>= 1) {
            sum += __shfl_xor_sync(0xffffffffu, sum, o);
            cnt += __shfl_xor_sync(0xffffffffu, cnt, o);
        }
        if (lane == 0) { ssum[warp] = sum; scnt[warp] = cnt; }
        __syncthreads();
        if (tid == 0) {
            float S = 0.0f, C = 0.0f;
#pragma unroll
            for (int w = 0; w < 8; w++) { S += ssum[w]; C += scnt[w]; }
            const int ci = (int)C;           // C <= 2048, exact in fp32
            s_tau  = (S - 1.0f) / C;         // C >= 1 always (diagonal valid)
            s_done = (ci == prev0) ? 1 : 0;  // support stable -> converged
            prev0  = ci;
        }
        __syncthreads();
        tau = s_tau;
        if (s_done) break;
    }

    // ---- deterministic compaction of nonzeros (z[x] > tau) ----
    // (masked cols are NEG_INF < tau, so they are automatically excluded)
    unsigned nzmask = 0u;
#pragma unroll
    for (int x = 0; x < 8; x++)
        if (z[x] > tau) nzmask |= (1u << x);

    int wcnt = __popc(nzmask);
#pragma unroll
    for (int o = 16; o > 0; o >>= 1) wcnt += __shfl_xor_sync(0xffffffffu, wcnt, o);
    if (lane == 0) siwarp[warp] = wcnt;
    __syncthreads();

    int wbase = 0;
#pragma unroll
    for (int w = 0; w < 8; w++)
        if (w < warp) wbase += siwarp[w];
    if (tid == 0) {
        int tot = 0;
#pragma unroll
        for (int w = 0; w < 8; w++) tot += siwarp[w];
        g_cnt[ch * L + row] = tot;
    }

    float2* lst = g_list + base;
    int off = wbase;
#pragma unroll
    for (int x = 0; x < 8; x++) {
        const unsigned b = __ballot_sync(0xffffffffu, (nzmask >> x) & 1u);
        if ((nzmask >> x) & 1u) {
            const int pos = off + __popc(b & ((1u << lane) - 1u));
            lst[pos] = make_float2(__int_as_float(j0 + x), z[x] - tau);
        }
        off += __popc(b);
    }
}

// ---------------------------------------------------------------------------
// Kernel 2: grouped 3x3 conv from SPARSE input + bias + causal zero.
// One block (256 thr) per (out-row i, group g). Thread t owns cols [8t,8t+8)
// for all 4 out-channels (acc in registers, statically indexed).
// Loops over the 12 tiny nonzero lists (rows i-1..i+1 x 4 in-ch); every
// thread broadcast-reads each nnz, only window-matching threads do FMAs.
// ---------------------------------------------------------------------------
__global__ __launch_bounds__(256) void conv_sparse_kernel(const float* __restrict__ weight,
                                                          const float* __restrict__ bias,
                                                          float* __restrict__ out)
{
    __shared__ float wsm[144];   // [4 oc][4 ic][3][3]
    __shared__ float bsm[4];

    const int i   = blockIdx.x;   // output row
    const int g   = blockIdx.y;   // group
    const int tid = threadIdx.x;
    const int j0  = tid * 8;

    if (tid < 144) wsm[tid] = weight[g * 144 + tid];
    if (tid < 4)   bsm[tid] = bias[g * 4 + tid];
    __syncthreads();

    // Threads whose whole window is above the diagonal: outputs are all zero.
    if (j0 > i) {
        const float4 zq = make_float4(0.f, 0.f, 0.f, 0.f);
#pragma unroll
        for (int o = 0; o < 4; o++) {
            float* ob = out + ((size_t)(g * 4 + o) * L + i) * (size_t)L + j0;
            *reinterpret_cast<float4*>(ob)     = zq;
            *reinterpret_cast<float4*>(ob + 4) = zq;
        }
        return;
    }

    float acc[4][8];
#pragma unroll
    for (int o = 0; o < 4; o++)
#pragma unroll
        for (int x = 0; x < 8; x++) acc[o][x] = 0.0f;

#pragma unroll
    for (int icc = 0; icc < 4; icc++) {
        const int gc = g * 4 + icc;
#pragma unroll
        for (int dr = 0; dr < 3; dr++) {
            const int r = i + dr - 1;
            if (r < 0 || r >= L) continue;
            const int cnt = g_cnt[gc * L + r];                 // uniform
            const float2* lst = g_list + ((size_t)gc * L + r) * (size_t)L;
            for (int n = 0; n < cnt; n++) {                    // uniform trip count
                const float2 e = lst[n];                       // broadcast load
                const int jc = __float_as_int(e.x);
                if (jc < j0 - 1 || jc > j0 + 8) continue;      // window test
                const float v = e.y;
#pragma unroll
                for (int x = 0; x < 8; x++) {
                    const int dc = jc - j0 - x + 1;            // kernel col tap
                    if (dc >= 0 && dc < 3) {
#pragma unroll
                        for (int o = 0; o < 4; o++)
                            acc[o][x] = fmaf(wsm[((o * 4 + icc) * 3 + dr) * 3 + dc], v, acc[o][x]);
                    }
                }
            }
        }
    }

    // ---- bias + causal mask + dense store ----
#pragma unroll
    for (int o = 0; o < 4; o++) {
        const float b = bsm[o];
        float v[8];
#pragma unroll
        for (int x = 0; x < 8; x++)
            v[x] = (j0 + x <= i) ? (acc[o][x] + b) : 0.0f;
        float4 v0, v1;
        v0.x=v[0]; v0.y=v[1]; v0.z=v[2]; v0.w=v[3];
        v1.x=v[4]; v1.y=v[5]; v1.z=v[6]; v1.w=v[7];
        float* ob = out + ((size_t)(g * 4 + o) * L + i) * (size_t)L + j0;
        *reinterpret_cast<float4*>(ob)     = v0;
        *reinterpret_cast<float4*>(ob + 4) = v1;
    }
}

// ---------------------------------------------------------------------------
extern "C" void kernel_launch(void* const* d_in, const int* in_sizes, int n_in,
                              void* d_out, int out_size)
{
    const float* scores = (const float*)d_in[0];
    const float* weight = (const float*)d_in[1];
    const float* bias   = (const float*)d_in[2];
    float* out = (float*)d_out;

    sparsemax_kernel<<<dim3(L, C_IN), 256>>>(scores);
    conv_sparse_kernel<<<dim3(L, GROUPS), 256>>>(weight, bias, out);
}

// round 5
// speedup vs baseline: 2.4209x; 1.3159x over previous
#include <cuda_runtime.h>
#include <cstdint>

#define L      2048
#define C_IN   16
#define GROUPS 4
#define NEG_INF -1000000000.0f

// Compressed sparsemax output: per (ch,row) a COLUMN-SORTED list of
// (col,val) nonzeros. Full-stride allocation => no overflow for any input.
// .x = column index as int bits, .y = prob value.
__device__ float2 g_list[(size_t)C_IN * L * L];
__device__ int    g_cnt[C_IN * L];

// ---------------------------------------------------------------------------
// Kernel 1: row-wise sparsemax (causal) -> sorted compressed nonzero list.
// One block (128 thr) per (channel,row); thread t owns cols [16t, 16t+16).
// Michelot's exact algorithm seeded at tau = rowmax - 1.
// One barrier per iteration (double-buffered partials, no serial combine).
// ---------------------------------------------------------------------------
__global__ __launch_bounds__(128) void sparsemax_kernel(const float* __restrict__ scores)
{
    const int row  = blockIdx.x;
    const int ch   = blockIdx.y;
    const int tid  = threadIdx.x;
    const int lane = tid & 31;
    const int warp = tid >> 5;            // 4 warps
    const size_t base = ((size_t)ch * L + row) * (size_t)L;
    const int j0  = tid * 16;
    const int rem = row - j0;             // valid elements: x <= rem

    float z[16];
    if (rem >= 15) {
#pragma unroll
        for (int q = 0; q < 4; q++) {
            const float4 a = *reinterpret_cast<const float4*>(scores + base + j0 + 4 * q);
            z[4*q+0]=a.x; z[4*q+1]=a.y; z[4*q+2]=a.z; z[4*q+3]=a.w;
        }
    } else {
#pragma unroll
        for (int x = 0; x < 16; x++)
            z[x] = (x <= rem) ? scores[base + j0 + x] : NEG_INF;
    }

    __shared__ float smax[4];
    __shared__ float ssum[2][4];
    __shared__ float scnt[2][4];
    __shared__ int   swtot[4];

    // ---- row max: warp reduce -> smem -> every thread combines ----
    float m = z[0];
#pragma unroll
    for (int k = 1; k < 16; k++) m = fmaxf(m, z[k]);
#pragma unroll
    for (int o = 16; o > 0; o >>= 1) m = fmaxf(m, __shfl_xor_sync(0xffffffffu, m, o));
    if (lane == 0) smax[warp] = m;
    __syncthreads();
    float tau = fmaxf(fmaxf(smax[0], smax[1]), fmaxf(smax[2], smax[3])) - 1.0f;

    // ---- Michelot iterations: 1 barrier each, uniform decisions ----
    int prev = -1;
    for (int it = 0; it < 32; it++) {
        float sum = 0.0f, cnt = 0.0f;
#pragma unroll
        for (int k = 0; k < 16; k++) {
            if (z[k] > tau) { sum += z[k]; cnt += 1.0f; }
        }
#pragma unroll
        for (int o = 16; o > 0; o >>= 1) {
            sum += __shfl_xor_sync(0xffffffffu, sum, o);
            cnt += __shfl_xor_sync(0xffffffffu, cnt, o);
        }
        const int sl = it & 1;
        if (lane == 0) { ssum[sl][warp] = sum; scnt[sl][warp] = cnt; }
        __syncthreads();
        const float S = ssum[sl][0] + ssum[sl][1] + ssum[sl][2] + ssum[sl][3];
        const float C = scnt[sl][0] + scnt[sl][1] + scnt[sl][2] + scnt[sl][3];
        const int  ci = (int)C;              // C <= 2048, exact in fp32; C >= 1 always
        tau = (S - 1.0f) / C;
        if (ci == prev) break;               // support stable (uniform across block)
        prev = ci;
    }

    // ---- column-sorted compaction (rank = exclusive scan of per-thread counts) ----
    unsigned nzmask = 0u;
#pragma unroll
    for (int x = 0; x < 16; x++)
        if (z[x] > tau) nzmask |= (1u << x);
    const int tcnt = __popc(nzmask);

    int v = tcnt;                             // warp inclusive scan
#pragma unroll
    for (int o = 1; o < 32; o <<= 1) {
        const int n = __shfl_up_sync(0xffffffffu, v, o);
        if (lane >= o) v += n;
    }
    const int toff = v - tcnt;
    const int wtot = __shfl_sync(0xffffffffu, v, 31);
    if (lane == 0) swtot[warp] = wtot;
    __syncthreads();

    int wbase = 0;
#pragma unroll
    for (int w = 0; w < 4; w++)
        if (w < warp) wbase += swtot[w];
    if (tid == 0)
        g_cnt[ch * L + row] = swtot[0] + swtot[1] + swtot[2] + swtot[3];

    // thread-local entries are ascending cols; threads ordered => global sort
    float2* lst = g_list + base;
    int pos = wbase + toff;
#pragma unroll
    for (int x = 0; x < 16; x++) {
        if ((nzmask >> x) & 1u) {
            lst[pos] = make_float2(__int_as_float(j0 + x), z[x] - tau);
            pos++;
        }
    }
}

// ---------------------------------------------------------------------------
// Kernel 2: grouped 3x3 conv from SORTED sparse lists + bias + causal zero.
// One block (256 thr) per (out-row i, group g). Warp w covers cols [256w,256w+256).
// 96 threads precompute per-(list,warp) [start,end) ranges; compute threads
// then touch only their warp's ~1-2 entries per list.
// ---------------------------------------------------------------------------
__global__ __launch_bounds__(256) void conv_sparse_kernel(const float* __restrict__ weight,
                                                          const float* __restrict__ bias,
                                                          float* __restrict__ out)
{
    __shared__ float wsm[144];       // [4 oc][4 ic][3][3]
    __shared__ float bsm[4];
    __shared__ int2  srange[12][8];  // [list p = icc*3+dr][warp]

    const int i    = blockIdx.x;     // output row
    const int g    = blockIdx.y;     // group
    const int tid  = threadIdx.x;
    const int warp = tid >> 5;
    const int j0   = tid * 8;

    if (tid < 144) wsm[tid] = weight[g * 144 + tid];
    if (tid < 4)   bsm[tid] = bias[g * 4 + tid];

    // ---- per-(list,warp) index ranges via monotone counting ----
    if (tid < 96) {
        const int p   = tid >> 3;          // 0..11
        const int w   = tid & 7;           // warp
        const int icc = p / 3;
        const int dr  = p - icc * 3;
        const int r   = i + dr - 1;
        int s = 0, e = 0;
        if (r >= 0 && r < L) {
            const int gc  = g * 4 + icc;
            const int cnt = g_cnt[gc * L + r];
            const float2* lst = g_list + ((size_t)gc * L + r) * (size_t)L;
            const int lo = w * 256 - 1;            // window min col for this warp
            const int hi = w * 256 + 256;          // window max col for this warp
            for (int n = 0; n < cnt; n++) {
                const int c = __float_as_int(lst[n].x);   // sorted ascending
                s += (c < lo);
                e += (c <= hi);
            }
        }
        srange[p][w] = make_int2(s, e);
    }
    __syncthreads();

    // ---- threads fully above the diagonal: zero-store and exit ----
    if (j0 > i) {
        const float4 zq = make_float4(0.f, 0.f, 0.f, 0.f);
#pragma unroll
        for (int o = 0; o < 4; o++) {
            float* ob = out + ((size_t)(g * 4 + o) * L + i) * (size_t)L + j0;
            *reinterpret_cast<float4*>(ob)     = zq;
            *reinterpret_cast<float4*>(ob + 4) = zq;
        }
        return;
    }

    float acc[4][8];
#pragma unroll
    for (int o = 0; o < 4; o++)
#pragma unroll
        for (int x = 0; x < 8; x++) acc[o][x] = 0.0f;

#pragma unroll
    for (int p = 0; p < 12; p++) {
        const int icc = p / 3;
        const int dr  = p - icc * 3;
        const int r   = i + dr - 1;
        if (r < 0 || r >= L) continue;
        const int gc = g * 4 + icc;
        const float2* lst = g_list + ((size_t)gc * L + r) * (size_t)L;
        const int2 se = srange[p][warp];
        for (int n = se.x; n < se.y; n++) {      // ~1-2 entries, warp-uniform
            const float2 e = lst[n];             // broadcast load (L1/L2 hot)
            const int jc = __float_as_int(e.x);
            if (jc < j0 - 1 || jc > j0 + 8) continue;
            const float v = e.y;
#pragma unroll
            for (int x = 0; x < 8; x++) {
                const int dc = jc - j0 - x + 1;  // kernel col tap
                if (dc >= 0 && dc < 3) {
#pragma unroll
                    for (int o = 0; o < 4; o++)
                        acc[o][x] = fmaf(wsm[((o * 4 + icc) * 3 + dr) * 3 + dc], v, acc[o][x]);
                }
            }
        }
    }

    // ---- bias + causal mask + dense store ----
#pragma unroll
    for (int o = 0; o < 4; o++) {
        const float b = bsm[o];
        float v[8];
#pragma unroll
        for (int x = 0; x < 8; x++)
            v[x] = (j0 + x <= i) ? (acc[o][x] + b) : 0.0f;
        float4 v0, v1;
        v0.x=v[0]; v0.y=v[1]; v0.z=v[2]; v0.w=v[3];
        v1.x=v[4]; v1.y=v[5]; v1.z=v[6]; v1.w=v[7];
        float* ob = out + ((size_t)(g * 4 + o) * L + i) * (size_t)L + j0;
        *reinterpret_cast<float4*>(ob)     = v0;
        *reinterpret_cast<float4*>(ob + 4) = v1;
    }
}

// ---------------------------------------------------------------------------
extern "C" void kernel_launch(void* const* d_in, const int* in_sizes, int n_in,
                              void* d_out, int out_size)
{
    const float* scores = (const float*)d_in[0];
    const float* weight = (const float*)d_in[1];
    const float* bias   = (const float*)d_in[2];
    float* out = (float*)d_out;

    sparsemax_kernel<<<dim3(L, C_IN), 128>>>(scores);
    conv_sparse_kernel<<<dim3(L, GROUPS), 256>>>(weight, bias, out);
}